// round 11
// baseline (speedup 1.0000x reference)
#include <cuda_runtime.h>
#include <cuda_fp16.h>
#include <cstdint>

#define B_   32
#define CI   64
#define CO   64
#define N_   4096
#define M1   1024      // modes1
#define K_   2049      // output length N/2+1
#define ROWS (B_*CI)   // 2048
#define NCAS 2304      // padded n rows for cas (9 * 256)

// -------- device scratch (static globals; no allocation) --------
__device__ float  g_tw[4096];                // butterfly twiddles: g_tw[h+j] = cas(2*pi*j/(2h))
__device__ __half g_casB[NCAS * M1];         // idht cas, fp16, chunk-major fragment layout
__device__ float  g_wp[M1 * 32 * CO];        // [k][i<32][o] = w[i,o,k] + w[63-i,o,k]
__device__ float  g_wm[M1 * 32 * CO];        // [k][i<32][o] = w[i,o,k] - w[63-i,o,k]
__device__ float  g_xh [ROWS * M1];          // FHT output, row-major: [row][k]  (coalesced writes)
__device__ float  g_xhT[M1 * ROWS];          // FHT output transposed, k-major: [k][row]
__device__ __half g_ohP[M1 * ROWS];          // mixed modes, plain k-major: [k][m] (coalesced writes)
__device__ __half g_ohA[ROWS * M1];          // mixed modes (A matrix), fp16, mma fragment layout

// ---- fragment layouts (half index) ----
// A(m, k):  c=k>>5, s=(k>>4)&1, t=(k>>1)&3, mrow=(m>>4)*8+(m&7),
//           j = (k&1) + 2*((m>>3)&1) + 4*((k>>3)&1)
//           idx = (((c*2+s)*1024 + mrow)*4 + t)*8 + j
// B(n, k):  c=k>>5, t=(k>>1)&3, j = (k&1) + 2*((k>>3)&1) + 4*((k>>4)&1)
//           idx = ((c*NCAS + n)*4 + t)*8 + j

#define TWO_PI_F 6.283185307179586f

// ================= setup kernels =================
__global__ void tw_kernel() {
    int t = blockIdx.x * blockDim.x + threadIdx.x;
    if (t < 1 || t >= 4096) return;
    int h = 1 << (31 - __clz(t));
    int j = t - h;
    float ang = (TWO_PI_F * (float)j) / (float)(2 * h);
    float s, c; sincosf(ang, &s, &c);
    g_tw[t] = c + s;
}

// cas values in B fragment layout; angle follows the reference's f32 op order,
// then exact mod-2pi reduction (13b+24b split) to keep sincosf on the fast path.
__global__ void cas_kernel() {
    long idx = (long)blockIdx.x * blockDim.x + threadIdx.x;
    if (idx >= (long)NCAS * M1) return;
    int j = (int)(idx & 7);
    int t = (int)((idx >> 3) & 3);
    long rest = idx >> 5;
    int n = (int)(rest % NCAS);
    int c = (int)(rest / NCAS);
    int k = c * 32 + ((j >> 2) & 1) * 16 + ((j >> 1) & 1) * 8 + t * 2 + (j & 1);
    float ang = (TWO_PI_F * ((float)k * (float)n)) / 2049.0f;   // <= ~7224
    float q = rintf(ang * 0.15915494309189535f);
    float r = fmaf(-q, 6.2822265625f, ang);                     // exact (13b*11b)
    r = fmaf(-q, 9.5874467958647648e-4f, r);                    // |r| <= pi + eps
    float s, c2; sincosf(r, &s, &c2);
    g_casB[idx] = __float2half(c2 + s);
}

// fold + transpose weights, halved via i<->63-i symmetry
__global__ void wpm_kernel(const float* __restrict__ w) {
    __shared__ float sp[32][33];
    __shared__ float sm[32][33];
    int i  = blockIdx.z;                // 0..31
    int o0 = blockIdx.y * 32;
    int k0 = blockIdx.x * 32;
    int tx = threadIdx.x, ty = threadIdx.y;
    size_t off1 = ((size_t)i        * CO + (o0 + ty)) * M1 + k0 + tx;
    size_t off2 = ((size_t)(63 - i) * CO + (o0 + ty)) * M1 + k0 + tx;
    float a = w[off1], b = w[off2];
    sp[ty][tx] = a + b;
    sm[ty][tx] = a - b;
    __syncthreads();
    size_t woff = (size_t)(k0 + ty) * (32 * CO) + (size_t)i * CO + (o0 + tx);
    g_wp[woff] = sp[tx][ty];
    g_wm[woff] = sm[tx][ty];
}

// ================= FHT: 3-phase register-resident radix-16 =================
__global__ void __launch_bounds__(256) fht_kernel(const float* __restrict__ x) {
    __shared__ float s[N_ + N_ / 16];
    const int tid = threadIdx.x;
    const int row = blockIdx.x;
    const float* xr = x + (size_t)row * N_;

#pragma unroll
    for (int it = 0; it < 4; it++) {
        int n = tid * 4 + it * 1024;
        float4 v = *(const float4*)(xr + n);
        int p = n + (n >> 4);
        s[p] = v.x; s[p + 1] = v.y; s[p + 2] = v.z; s[p + 3] = v.w;
    }
    __syncthreads();

    float r[16];
    const int bt = __brev((unsigned)tid) >> 24;
#pragma unroll
    for (int q = 0; q < 16; q++) {
        int br = __brev((unsigned)q) >> 28;
        int idx = br * 256 + bt;
        r[q] = s[idx + (idx >> 4)];
    }
#pragma unroll
    for (int hs = 1; hs <= 8; hs <<= 1) {
#pragma unroll
        for (int q = 0; q < 16; q++) {
            if ((q & hs) == 0) {
                float tw = g_tw[hs + (q & (hs - 1))];
                float u = r[q], v = r[q + hs];
                float tv = tw * v;
                r[q] = u + tv; r[q + hs] = u - tv;
            }
        }
    }
    __syncthreads();
#pragma unroll
    for (int q = 0; q < 16; q++) {
        int idx = 16 * tid + q;
        s[idx + (idx >> 4)] = r[q];
    }
    __syncthreads();

    const int hi = tid >> 4, lo = tid & 15;
#pragma unroll
    for (int q = 0; q < 16; q++) {
        int idx = hi * 256 + q * 16 + lo;
        r[q] = s[idx + (idx >> 4)];
    }
#pragma unroll
    for (int hb = 1; hb <= 8; hb <<= 1) {
        int h = hb * 16;
#pragma unroll
        for (int q = 0; q < 16; q++) {
            if ((q & hb) == 0) {
                float tw = g_tw[h + (q & (hb - 1)) * 16 + lo];
                float u = r[q], v = r[q + hb];
                float tv = tw * v;
                r[q] = u + tv; r[q + hb] = u - tv;
            }
        }
    }
    __syncthreads();
#pragma unroll
    for (int q = 0; q < 16; q++) {
        int idx = hi * 256 + q * 16 + lo;
        s[idx + (idx >> 4)] = r[q];
    }
    __syncthreads();

#pragma unroll
    for (int q = 0; q < 16; q++) {
        int idx = q * 256 + tid;
        r[q] = s[idx + (idx >> 4)];
    }
#pragma unroll
    for (int hb = 1; hb <= 8; hb <<= 1) {
        int h = hb * 256;
#pragma unroll
        for (int q = 0; q < 16; q++) {
            if ((q & hb) == 0) {
                float tw = g_tw[h + (q & (hb - 1)) * 256 + tid];
                float u = r[q], v = r[q + hb];
                float tv = tw * v;
                r[q] = u + tv; r[q + hb] = u - tv;
            }
        }
    }
    // coalesced row-major write of first M1 modes
#pragma unroll
    for (int q = 0; q < 4; q++)
        g_xh[(size_t)row * M1 + q * 256 + tid] = r[q];
}

// ================= transpose: g_xh[2048][1024] -> g_xhT[1024][2048] =================
__global__ void __launch_bounds__(256) tr_kernel() {
    __shared__ float t[32][33];
    int c0 = blockIdx.x * 32;   // k
    int r0 = blockIdx.y * 32;   // row
    int tx = threadIdx.x, ty = threadIdx.y;
#pragma unroll
    for (int i = ty; i < 32; i += 8)
        t[i][tx] = g_xh[(size_t)(r0 + i) * M1 + c0 + tx];
    __syncthreads();
#pragma unroll
    for (int i = ty; i < 32; i += 8)
        g_xhT[(size_t)(c0 + i) * ROWS + r0 + tx] = t[tx][i];
}

// ================= mode mixing: 2 k's/block, 64 thr/k, float4 W loads =================
__global__ void __launch_bounds__(128) mix_kernel() {
    __shared__ float sYp[2][B_ * 32];
    __shared__ float sYm[2][B_ * 32];
    __shared__ float sWp[2][32 * CO];
    __shared__ float sWm[2][32 * CO];
    const int k0 = blockIdx.x * 2;
    const int tid = threadIdx.x;

    // fold X into Yp/Ym (i<32)
    for (int idx = tid; idx < 2 * ROWS; idx += 128) {
        int kk = idx >> 11;
        int j  = idx & 2047;
        int b = j >> 6, i = j & 63;
        if (i < 32) {
            const float* Xk = g_xhT + (size_t)(k0 + kk) * ROWS;
            float u = Xk[b * 64 + i], v = Xk[b * 64 + 63 - i];
            sYp[kk][b * 32 + i] = u + v;
            sYm[kk][b * 32 + i] = u - v;
        }
    }
    // load W
    for (int idx = tid; idx < 2 * 2048; idx += 128) {
        int kk = idx >> 11, j = idx & 2047;
        sWp[kk][j] = g_wp[(size_t)(k0 + kk) * 2048 + j];
        sWm[kk][j] = g_wm[(size_t)(k0 + kk) * 2048 + j];
    }
    __syncthreads();

    const int kk = tid >> 6;
    const int t  = tid & 63;
    const int oq = t & 15;          // o = oq*4 .. +3
    const int bq = t >> 4;          // b = bq*8 .. +7

    float acc[8][4];
#pragma unroll
    for (int rr = 0; rr < 8; rr++)
#pragma unroll
        for (int c = 0; c < 4; c++) acc[rr][c] = 0.f;

    for (int i = 0; i < 32; i++) {
        float4 wpv = *(const float4*)&sWp[kk][i * CO + oq * 4];
        float4 wmv = *(const float4*)&sWm[kk][i * CO + oq * 4];
#pragma unroll
        for (int rr = 0; rr < 8; rr++) {
            int b = bq * 8 + rr;
            float yp = sYp[kk][b * 32 + i];
            float ym = sYm[kk][(31 - b) * 32 + i];
            acc[rr][0] += yp * wpv.x + ym * wmv.x;
            acc[rr][1] += yp * wpv.y + ym * wmv.y;
            acc[rr][2] += yp * wpv.z + ym * wmv.z;
            acc[rr][3] += yp * wpv.w + ym * wmv.w;
        }
    }

    __half* ok = g_ohP + (size_t)(k0 + kk) * ROWS;
#pragma unroll
    for (int rr = 0; rr < 8; rr++) {
        int m = (bq * 8 + rr) * 64 + oq * 4;
        __half2 h0 = __floats2half2_rn(0.5f * acc[rr][0], 0.5f * acc[rr][1]);
        __half2 h1 = __floats2half2_rn(0.5f * acc[rr][2], 0.5f * acc[rr][3]);
        uint2 v; v.x = *(uint32_t*)&h0; v.y = *(uint32_t*)&h1;
        *(uint2*)&ok[m] = v;    // 8B per thread, contiguous across oq
    }
}

// ================= repack A: plain k-major -> mma fragment layout =================
__global__ void __launch_bounds__(256) repackA_kernel() {
    __shared__ __half sT[32 * 256];     // [kk][m_local]
    const int c  = blockIdx.y;          // k-chunk 0..31
    const int m0 = blockIdx.x * 256;    // m tile
    const int tid = threadIdx.x;
    const uint4* inU = (const uint4*)g_ohP;
#pragma unroll
    for (int it = 0; it < 4; it++) {
        int kk = it * 8 + (tid >> 5);
        int u  = tid & 31;
        ((uint4*)sT)[kk * 32 + u] = inU[(long)(c * 32 + kk) * 256 + (m0 >> 3) + u];
    }
    __syncthreads();
    uint4* outU = (uint4*)g_ohA;
#pragma unroll
    for (int ii = 0; ii < 4; ii++) {
        int idx = ii * 256 + tid;                 // 0..1023
        int s   = idx >> 9;
        int rem = idx & 511;
        int mrl = rem >> 2;                       // mrow local 0..127
        int t   = rem & 3;
        uint32_t p[4];
#pragma unroll
        for (int jp = 0; jp < 4; jp++) {          // j = jp*2, jp*2+1
            int j0 = jp * 2;
            int kk0 = s * 16 + t * 2 + 8 * ((j0 >> 2) & 1);
            int ml0 = ((mrl >> 3) << 4) + 8 * ((j0 >> 1) & 1) + (mrl & 7);
            uint32_t lo = __half_as_ushort(sT[kk0 * 256 + ml0]);
            uint32_t hi = __half_as_ushort(sT[(kk0 + 1) * 256 + ml0]);
            p[jp] = lo | (hi << 16);
        }
        uint4 v; v.x = p[0]; v.y = p[1]; v.z = p[2]; v.w = p[3];
        outU[((long)(c * 2 + s) * 1024 + (m0 >> 1) + mrl) * 4 + t] = v;
    }
}

// ================= idht GEMM: mma.sync fp16, smem-free (R9 config) =================
// CTA tile 64m x 256n, 256 threads (8 warps, 2 wm x 4 wn), warp tile 32x64.
#define GNCH 32

#define MMA16(d, a, b0, b1) \
    asm volatile("mma.sync.aligned.m16n8k16.row.col.f32.f16.f16.f32 " \
        "{%0,%1,%2,%3}, {%4,%5,%6,%7}, {%8,%9}, {%0,%1,%2,%3};" \
        : "+f"((d)[0]), "+f"((d)[1]), "+f"((d)[2]), "+f"((d)[3]) \
        : "r"((a).x), "r"((a).y), "r"((a).z), "r"((a).w), "r"(b0), "r"(b1))

__global__ void __launch_bounds__(256, 2) gemm_kernel(float* __restrict__ out) {
    const int tid  = threadIdx.x;
    const int wid  = tid >> 5;
    const int lane = tid & 31;
    const int g    = lane >> 2;        // fragment row group
    const int t    = lane & 3;         // fragment k-slot
    const int wm   = wid & 1;          // warp M strip (0..1)
    const int wn   = wid >> 1;         // warp N strip (0..3)
    const int m0   = blockIdx.y * 64;
    const int n0   = blockIdx.x * 256;

    const int m_base = m0 + wm * 32;
    const int n_base = n0 + wn * 64;
    const int mr8    = m_base >> 4;    // mrow block (x8)

    const uint4* Au = (const uint4*)g_ohA;   // [(c*2+s)*1024 + mrow][t]
    const uint4* Bu = (const uint4*)g_casB;  // [c*NCAS + n][t]

    float acc[2][8][4];
#pragma unroll
    for (int a = 0; a < 2; a++)
#pragma unroll
        for (int b = 0; b < 8; b++)
#pragma unroll
            for (int c = 0; c < 4; c++) acc[a][b][c] = 0.f;

#pragma unroll 2
    for (int c = 0; c < GNCH; c++) {
        uint4 af[2][2], bf[8];
#pragma unroll
        for (int s = 0; s < 2; s++)
#pragma unroll
            for (int mt = 0; mt < 2; mt++)
                af[mt][s] = __ldg(Au + ((long)(c * 2 + s) * 1024 + (mr8 + mt) * 8 + g) * 4 + t);
#pragma unroll
        for (int nt = 0; nt < 8; nt++)
            bf[nt] = __ldg(Bu + ((long)c * NCAS + n_base + nt * 8 + g) * 4 + t);
#pragma unroll
        for (int nt = 0; nt < 8; nt++) {
#pragma unroll
            for (int mt = 0; mt < 2; mt++) {
                MMA16(acc[mt][nt], af[mt][0], bf[nt].x, bf[nt].y);
                MMA16(acc[mt][nt], af[mt][1], bf[nt].z, bf[nt].w);
            }
        }
    }

    // ---- epilogue ----
    const float inv = 1.0f / 2049.0f;
#pragma unroll
    for (int mt = 0; mt < 2; mt++) {
        int row = m_base + mt * 16 + g;
#pragma unroll
        for (int nt = 0; nt < 8; nt++) {
            int col = n_base + nt * 8 + t * 2;
            if (col < K_) {
                float* p0 = out + (size_t)row * K_ + col;
                float* p1 = out + (size_t)(row + 8) * K_ + col;
                p0[0] = acc[mt][nt][0] * inv;
                p1[0] = acc[mt][nt][2] * inv;
                if (col + 1 < K_) {
                    p0[1] = acc[mt][nt][1] * inv;
                    p1[1] = acc[mt][nt][3] * inv;
                }
            }
        }
    }
}

// ================= launch =================
extern "C" void kernel_launch(void* const* d_in, const int* in_sizes, int n_in,
                              void* d_out, int out_size) {
    const float* x = (const float*)d_in[0];
    const float* w = (const float*)d_in[1];
    float* out = (float*)d_out;

    tw_kernel<<<16, 256>>>();
    cas_kernel<<<(NCAS * M1 + 255) / 256, 256>>>();
    wpm_kernel<<<dim3(32, 2, 32), dim3(32, 32)>>>(w);
    fht_kernel<<<ROWS, 256>>>(x);
    tr_kernel<<<dim3(M1 / 32, ROWS / 32), dim3(32, 8)>>>();
    mix_kernel<<<M1 / 2, 128>>>();
    repackA_kernel<<<dim3(ROWS / 256, 32), 256>>>();
    gemm_kernel<<<dim3(NCAS / 256, ROWS / 64), 256>>>(out);
}

// round 15
// speedup vs baseline: 1.2225x; 1.2225x over previous
#include <cuda_runtime.h>
#include <cuda_fp16.h>
#include <cstdint>

#define B_   32
#define CI   64
#define CO   64
#define N_   4096
#define M1   1024      // modes1
#define K_   2049      // output length N/2+1
#define ROWS (B_*CI)   // 2048
#define NCAS 2304      // padded n rows for cas (9 * 256)

// -------- device scratch (static globals; no allocation) --------
__device__ float  g_tw[4096];                // butterfly twiddles: g_tw[h+j] = cas(2*pi*j/(2h))
__device__ __half g_casB[NCAS * M1];         // idht cas, fp16, chunk-major B fragment layout
__device__ __half g_wph[M1 * 32 * CO];       // fp16 [k][i<32][o] = w[i,o,k] + w[63-i,o,k]
__device__ __half g_wmh[M1 * 32 * CO];       // fp16 [k][i<32][o] = w[i,o,k] - w[63-i,o,k]
__device__ float  g_xh [ROWS * M1];          // FHT output, row-major: [row][k]
__device__ __half g_ohA[ROWS * M1];          // A matrix, fp16, mma fragment layout

// ---- fragment layouts (half index) ----
// A(m, k):  c=k>>5, s=(k>>4)&1, t=(k>>1)&3, mrow=(m>>4)*8+(m&7),
//           j = (k&1) + 2*((m>>3)&1) + 4*((k>>3)&1)
//           idx = (((c*2+s)*1024 + mrow)*4 + t)*8 + j
// B(n, k):  c=k>>5, t=(k>>1)&3, j = (k&1) + 2*((k>>3)&1) + 4*((k>>4)&1)
//           idx = ((c*NCAS + n)*4 + t)*8 + j

#define TWO_PI_F 6.283185307179586f

// ================= tw: MUST run before prep (fht reads g_tw) =================
__global__ void tw_kernel() {
    int t = blockIdx.x * blockDim.x + threadIdx.x;
    if (t < 1 || t >= 4096) return;
    int h = 1 << (31 - __clz(t));
    int j = t - h;
    float ang = (TWO_PI_F * (float)j) / (float)(2 * h);
    float s, c; sincosf(ang, &s, &c);
    g_tw[t] = c + s;
}

// ================= prep: fht + wpm + cas fused by block range =================
// blocks [0,2048)            : fht rows
// blocks [2048,4096)         : wpm tiles (32k x 2o x 32i)
// blocks [4096,4096+9216)    : cas
#define PREP_BLOCKS (2048 + 2048 + 9216)

__global__ void __launch_bounds__(256) prep_kernel(const float* __restrict__ x,
                                                   const float* __restrict__ w) {
    __shared__ float sbuf[N_ + N_ / 16];    // 4352 floats; fht uses all, wpm uses 2112
    const int bid = blockIdx.x;
    const int tid = threadIdx.x;

    if (bid < 2048) {
        // ---------------- FHT: 3-phase register-resident radix-16 ----------------
        float* s = sbuf;
        const int row = bid;
        const float* xr = x + (size_t)row * N_;
#pragma unroll
        for (int it = 0; it < 4; it++) {
            int n = tid * 4 + it * 1024;
            float4 v = *(const float4*)(xr + n);
            int p = n + (n >> 4);
            s[p] = v.x; s[p + 1] = v.y; s[p + 2] = v.z; s[p + 3] = v.w;
        }
        __syncthreads();

        float r[16];
        const int bt = __brev((unsigned)tid) >> 24;
#pragma unroll
        for (int q = 0; q < 16; q++) {
            int br = __brev((unsigned)q) >> 28;
            int idx = br * 256 + bt;
            r[q] = s[idx + (idx >> 4)];
        }
#pragma unroll
        for (int hs = 1; hs <= 8; hs <<= 1) {
#pragma unroll
            for (int q = 0; q < 16; q++) {
                if ((q & hs) == 0) {
                    float tw = g_tw[hs + (q & (hs - 1))];
                    float u = r[q], v = r[q + hs];
                    float tv = tw * v;
                    r[q] = u + tv; r[q + hs] = u - tv;
                }
            }
        }
        __syncthreads();
#pragma unroll
        for (int q = 0; q < 16; q++) {
            int idx = 16 * tid + q;
            s[idx + (idx >> 4)] = r[q];
        }
        __syncthreads();

        const int hi = tid >> 4, lo = tid & 15;
#pragma unroll
        for (int q = 0; q < 16; q++) {
            int idx = hi * 256 + q * 16 + lo;
            r[q] = s[idx + (idx >> 4)];
        }
#pragma unroll
        for (int hb = 1; hb <= 8; hb <<= 1) {
            int h = hb * 16;
#pragma unroll
            for (int q = 0; q < 16; q++) {
                if ((q & hb) == 0) {
                    float tw = g_tw[h + (q & (hb - 1)) * 16 + lo];
                    float u = r[q], v = r[q + hb];
                    float tv = tw * v;
                    r[q] = u + tv; r[q + hb] = u - tv;
                }
            }
        }
        __syncthreads();
#pragma unroll
        for (int q = 0; q < 16; q++) {
            int idx = hi * 256 + q * 16 + lo;
            s[idx + (idx >> 4)] = r[q];
        }
        __syncthreads();

#pragma unroll
        for (int q = 0; q < 16; q++) {
            int idx = q * 256 + tid;
            r[q] = s[idx + (idx >> 4)];
        }
#pragma unroll
        for (int hb = 1; hb <= 8; hb <<= 1) {
            int h = hb * 256;
#pragma unroll
            for (int q = 0; q < 16; q++) {
                if ((q & hb) == 0) {
                    float tw = g_tw[h + (q & (hb - 1)) * 256 + tid];
                    float u = r[q], v = r[q + hb];
                    float tv = tw * v;
                    r[q] = u + tv; r[q + hb] = u - tv;
                }
            }
        }
#pragma unroll
        for (int q = 0; q < 4; q++)
            g_xh[(size_t)row * M1 + q * 256 + tid] = r[q];

    } else if (bid < 4096) {
        // ---------------- wpm: fold + transpose weights -> fp16 ----------------
        float* sp = sbuf;                 // [32][33]
        float* sm = sbuf + 1056;          // [32][33]
        const int b2 = bid - 2048;
        const int i  = b2 & 31;
        const int o0 = ((b2 >> 5) & 1) * 32;
        const int k0 = (b2 >> 6) * 32;
        const int tx = tid & 31;
        const int ty8 = tid >> 5;
#pragma unroll
        for (int tt = 0; tt < 4; tt++) {
            int ty = ty8 * 4 + tt;
            size_t off1 = ((size_t)i        * CO + (o0 + ty)) * M1 + k0 + tx;
            size_t off2 = ((size_t)(63 - i) * CO + (o0 + ty)) * M1 + k0 + tx;
            float a = w[off1], b = w[off2];
            sp[ty * 33 + tx] = a + b;
            sm[ty * 33 + tx] = a - b;
        }
        __syncthreads();
#pragma unroll
        for (int tt = 0; tt < 4; tt++) {
            int ty = ty8 * 4 + tt;
            size_t woff = (size_t)(k0 + ty) * (32 * CO) + (size_t)i * CO + (o0 + tx);
            g_wph[woff] = __float2half(sp[tx * 33 + ty]);
            g_wmh[woff] = __float2half(sm[tx * 33 + ty]);
        }

    } else {
        // ---------------- cas: B fragment layout, exact mod-2pi reduction ----------------
        long idx = (long)(bid - 4096) * 256 + tid;
        if (idx < (long)NCAS * M1) {
            int j = (int)(idx & 7);
            int t = (int)((idx >> 3) & 3);
            long rest = idx >> 5;
            int n = (int)(rest % NCAS);
            int c = (int)(rest / NCAS);
            int k = c * 32 + ((j >> 2) & 1) * 16 + ((j >> 1) & 1) * 8 + t * 2 + (j & 1);
            float ang = (TWO_PI_F * ((float)k * (float)n)) / 2049.0f;
            float q = rintf(ang * 0.15915494309189535f);
            float r = fmaf(-q, 6.2822265625f, ang);
            r = fmaf(-q, 9.5874467958647648e-4f, r);
            float s, c2; sincosf(r, &s, &c2);
            g_casB[idx] = __float2half(c2 + s);
        }
    }
}

// ================= mixPack: mix + transpose-read + A fragment pack =================
// Block: 8 consecutive k's (k0 = blockIdx.x*8), 256 threads, 64KB dynamic smem.
__global__ void __launch_bounds__(256) mixPack_kernel() {
    extern __shared__ float sX[];          // [8][2048] raw X -> folded Yp/Ym; reused as half out
    const int k0  = blockIdx.x * 8;
    const int tid = threadIdx.x;

    // ---- load: 8 floats per row (32B, sector-efficient) ----
#pragma unroll
    for (int jr = 0; jr < 8; jr++) {
        int r = tid + 256 * jr;
        const float* p = g_xh + (size_t)r * M1 + k0;
        float4 a = *(const float4*)p;
        float4 b = *(const float4*)(p + 4);
        sX[0 * 2048 + r] = a.x; sX[1 * 2048 + r] = a.y;
        sX[2 * 2048 + r] = a.z; sX[3 * 2048 + r] = a.w;
        sX[4 * 2048 + r] = b.x; sX[5 * 2048 + r] = b.y;
        sX[6 * 2048 + r] = b.z; sX[7 * 2048 + r] = b.w;
    }
    __syncthreads();

    // ---- fold in place: [b*64+i] <- Yp, [b*64+63-i] <- Ym  (i<32) ----
#pragma unroll
    for (int jj = 0; jj < 32; jj++) {
        int idx = tid + 256 * jj;          // 0..8191
        int kk = idx >> 10;
        int rem = idx & 1023;
        int b = rem >> 5, i = rem & 31;
        int base = kk * 2048 + b * 64;
        float u = sX[base + i], v = sX[base + 63 - i];
        sX[base + i]      = u + v;
        sX[base + 63 - i] = u - v;
    }
    __syncthreads();

    // ---- compute: 32 threads per k (oq<16 x bh<2), 16 b x 4 o per thread ----
    const int kk   = tid >> 5;
    const int lane = tid & 31;
    const int oq   = lane & 15;
    const int bh   = lane >> 4;
    const int k    = k0 + kk;

    float acc[16][4];
#pragma unroll
    for (int rr = 0; rr < 16; rr++)
#pragma unroll
        for (int c = 0; c < 4; c++) acc[rr][c] = 0.f;

    const __half* wph = g_wph + (size_t)k * 2048 + oq * 4;
    const __half* wmh = g_wmh + (size_t)k * 2048 + oq * 4;
    const float* Xk = sX + kk * 2048;

    for (int i = 0; i < 32; i++) {
        uint2 wpu = *(const uint2*)(wph + i * 64);
        uint2 wmu = *(const uint2*)(wmh + i * 64);
        float2 wp01 = __half22float2(*(__half2*)&wpu.x);
        float2 wp23 = __half22float2(*(__half2*)&wpu.y);
        float2 wm01 = __half22float2(*(__half2*)&wmu.x);
        float2 wm23 = __half22float2(*(__half2*)&wmu.y);
#pragma unroll
        for (int rr = 0; rr < 16; rr++) {
            int b = bh * 16 + rr;
            float yp = Xk[b * 64 + i];
            float ym = Xk[(31 - b) * 64 + 63 - i];
            acc[rr][0] += yp * wp01.x + ym * wm01.x;
            acc[rr][1] += yp * wp01.y + ym * wm01.y;
            acc[rr][2] += yp * wp23.x + ym * wm23.x;
            acc[rr][3] += yp * wp23.y + ym * wm23.y;
        }
    }
    __syncthreads();    // all X reads done before overwrite

    // ---- stage fp16 results: outH[kk][m], m = b*64 + oq*4 ----
    __half* outH = (__half*)sX;
#pragma unroll
    for (int rr = 0; rr < 16; rr++) {
        int b = bh * 16 + rr;
        int m = b * 64 + oq * 4;
        __half2 h0 = __floats2half2_rn(0.5f * acc[rr][0], 0.5f * acc[rr][1]);
        __half2 h1 = __floats2half2_rn(0.5f * acc[rr][2], 0.5f * acc[rr][3]);
        uint2 v; v.x = *(uint32_t*)&h0; v.y = *(uint32_t*)&h1;
        *(uint2*)(outH + kk * 2048 + m) = v;
    }
    __syncthreads();

    // ---- repack into A fragment layout: block owns 8B half of each uint4 ----
    const int cs = k0 >> 4;               // c*2 + s
    const int b3 = (k0 >> 3) & 1;
    char* dst = (char*)g_ohA;
#pragma unroll
    for (int jj = 0; jj < 16; jj++) {
        int idx = tid + 256 * jj;          // 0..4095
        int tq   = idx & 3;                // t
        int mrow = idx >> 2;               // 0..1023
        int m_e = ((mrow >> 3) << 4) + (mrow & 7);
        int m_o = m_e + 8;
        uint32_t e0 = __half_as_ushort(outH[(2 * tq)     * 2048 + m_e]);
        uint32_t o0 = __half_as_ushort(outH[(2 * tq + 1) * 2048 + m_e]);
        uint32_t e1 = __half_as_ushort(outH[(2 * tq)     * 2048 + m_o]);
        uint32_t o1 = __half_as_ushort(outH[(2 * tq + 1) * 2048 + m_o]);
        uint2 v; v.x = e0 | (o0 << 16); v.y = e1 | (o1 << 16);
        long byte = ((long)(cs * 1024 + mrow) * 4 + tq) * 16 + b3 * 8;
        *(uint2*)(dst + byte) = v;
    }
}

// ================= idht GEMM: mma.sync fp16, smem-free (R9 config) =================
#define GNCH 32

#define MMA16(d, a, b0, b1) \
    asm volatile("mma.sync.aligned.m16n8k16.row.col.f32.f16.f16.f32 " \
        "{%0,%1,%2,%3}, {%4,%5,%6,%7}, {%8,%9}, {%0,%1,%2,%3};" \
        : "+f"((d)[0]), "+f"((d)[1]), "+f"((d)[2]), "+f"((d)[3]) \
        : "r"((a).x), "r"((a).y), "r"((a).z), "r"((a).w), "r"(b0), "r"(b1))

__global__ void __launch_bounds__(256, 2) gemm_kernel(float* __restrict__ out) {
    const int tid  = threadIdx.x;
    const int wid  = tid >> 5;
    const int lane = tid & 31;
    const int g    = lane >> 2;
    const int t    = lane & 3;
    const int wm   = wid & 1;
    const int wn   = wid >> 1;
    const int m0   = blockIdx.y * 64;
    const int n0   = blockIdx.x * 256;

    const int m_base = m0 + wm * 32;
    const int n_base = n0 + wn * 64;
    const int mr8    = m_base >> 4;

    const uint4* Au = (const uint4*)g_ohA;
    const uint4* Bu = (const uint4*)g_casB;

    float acc[2][8][4];
#pragma unroll
    for (int a = 0; a < 2; a++)
#pragma unroll
        for (int b = 0; b < 8; b++)
#pragma unroll
            for (int c = 0; c < 4; c++) acc[a][b][c] = 0.f;

#pragma unroll 2
    for (int c = 0; c < GNCH; c++) {
        uint4 af[2][2], bf[8];
#pragma unroll
        for (int s = 0; s < 2; s++)
#pragma unroll
            for (int mt = 0; mt < 2; mt++)
                af[mt][s] = __ldg(Au + ((long)(c * 2 + s) * 1024 + (mr8 + mt) * 8 + g) * 4 + t);
#pragma unroll
        for (int nt = 0; nt < 8; nt++)
            bf[nt] = __ldg(Bu + ((long)c * NCAS + n_base + nt * 8 + g) * 4 + t);
#pragma unroll
        for (int nt = 0; nt < 8; nt++) {
#pragma unroll
            for (int mt = 0; mt < 2; mt++) {
                MMA16(acc[mt][nt], af[mt][0], bf[nt].x, bf[nt].y);
                MMA16(acc[mt][nt], af[mt][1], bf[nt].z, bf[nt].w);
            }
        }
    }

    const float inv = 1.0f / 2049.0f;
#pragma unroll
    for (int mt = 0; mt < 2; mt++) {
        int row = m_base + mt * 16 + g;
#pragma unroll
        for (int nt = 0; nt < 8; nt++) {
            int col = n_base + nt * 8 + t * 2;
            if (col < K_) {
                float* p0 = out + (size_t)row * K_ + col;
                float* p1 = out + (size_t)(row + 8) * K_ + col;
                p0[0] = acc[mt][nt][0] * inv;
                p1[0] = acc[mt][nt][2] * inv;
                if (col + 1 < K_) {
                    p0[1] = acc[mt][nt][1] * inv;
                    p1[1] = acc[mt][nt][3] * inv;
                }
            }
        }
    }
}

// ================= launch =================
extern "C" void kernel_launch(void* const* d_in, const int* in_sizes, int n_in,
                              void* d_out, int out_size) {
    const float* x = (const float*)d_in[0];
    const float* w = (const float*)d_in[1];
    float* out = (float*)d_out;

    cudaFuncSetAttribute(mixPack_kernel, cudaFuncAttributeMaxDynamicSharedMemorySize, 65536);

    tw_kernel<<<16, 256>>>();                      // fht reads g_tw: must precede prep
    prep_kernel<<<PREP_BLOCKS, 256>>>(x, w);
    mixPack_kernel<<<M1 / 8, 256, 65536>>>();
    gemm_kernel<<<dim3(NCAS / 256, ROWS / 64), 256>>>(out);
}